// round 2
// baseline (speedup 1.0000x reference)
#include <cuda_runtime.h>
#include <cuda_bf16.h>

// WKV (RWKV) operator: B=4, T=4096, H=2048, fp32.
// Chunked parallel scan: per-channel recurrence
//   a' = ew*a + exp(k)*v ;  b' = ew*b + exp(k)
// is affine with constant per-channel decay ew, so it splits into NC chunks
// of CL steps; cross-chunk combine uses eL = ew^CL.
//
// Kernel 1: per-(batch,chunk,channel-pair) local endpoint sums (zero init).
// Kernel 2: recompute the incoming prefix from the (L2-resident, 2 MB) chunk
//           sums, then re-run the exact reference recurrence within the chunk,
//           emitting wkv_t and the final (a, b).

#define B_ 4
#define T_ 4096
#define H_ 2048
#define H2_ 1024        // H/2 (float2 lanes)
#define NC_ 32          // number of chunks
#define CL_ 128         // chunk length = T/NC
#define H2SHIFT_ 10     // log2(H2_)
#define CSHIFT_ 5       // log2(NC_)

// Scratch (allocation-free rule: __device__ globals). 2 x 1 MB, L2-resident.
__device__ float2 g_cA[B_ * NC_ * H2_];
__device__ float2 g_cB[B_ * NC_ * H2_];

__device__ __forceinline__ float2 decay2(const float* td, int h2) {
    float2 t = ((const float2*)td)[h2];
    return make_float2(__expf(-__expf(t.x)), __expf(-__expf(t.y)));
}

// ---------------------------------------------------------------------------
// Kernel 1: chunk-local sums. One thread per (b, c, h2); h2 fastest dim so
// adjacent threads issue adjacent LDG.64 -> perfectly coalesced.
// ---------------------------------------------------------------------------
__global__ void __launch_bounds__(256) wkv_sums(
    const float* __restrict__ k, const float* __restrict__ v,
    const float* __restrict__ td)
{
    int idx = blockIdx.x * blockDim.x + threadIdx.x;   // (b*NC + c)*H2 + h2
    int h2 = idx & (H2_ - 1);
    int bc = idx >> H2SHIFT_;
    int c  = bc & (NC_ - 1);
    int b  = bc >> CSHIFT_;

    float2 ew = decay2(td, h2);

    size_t base2 = ((size_t)b * T_ + (size_t)c * CL_) * H2_ + h2;
    const float2* kp = (const float2*)k + base2;
    const float2* vp = (const float2*)v + base2;

    float ax = 0.0f, ay = 0.0f, bx = 0.0f, by = 0.0f;
    #pragma unroll 8
    for (int t = 0; t < CL_; ++t) {
        float2 kk = __ldg(kp + (size_t)t * H2_);
        float2 vv = __ldg(vp + (size_t)t * H2_);
        float ekx = __expf(kk.x);
        float eky = __expf(kk.y);
        ax = fmaf(ew.x, ax, ekx * vv.x);
        ay = fmaf(ew.y, ay, eky * vv.y);
        bx = fmaf(ew.x, bx, ekx);
        by = fmaf(ew.y, by, eky);
    }
    g_cA[idx] = make_float2(ax, ay);
    g_cB[idx] = make_float2(bx, by);
}

// ---------------------------------------------------------------------------
// Kernel 2: prefix combine (from L2-resident chunk sums) + in-chunk
// recurrence, exactly matching the reference (wkv emitted before the update).
// ---------------------------------------------------------------------------
__global__ void __launch_bounds__(256) wkv_out(
    const float* __restrict__ k, const float* __restrict__ v,
    const float* __restrict__ td, const float* __restrict__ tf,
    float* __restrict__ out, float* __restrict__ outA, float* __restrict__ outB,
    int write_ab)
{
    int idx = blockIdx.x * blockDim.x + threadIdx.x;   // (b*NC + c)*H2 + h2
    int h2 = idx & (H2_ - 1);
    int bc = idx >> H2SHIFT_;
    int c  = bc & (NC_ - 1);
    int b  = bc >> CSHIFT_;

    float2 ew = decay2(td, h2);
    float2 tfv = ((const float2*)tf)[h2];
    float eux = __expf(tfv.x);           // exp(u); exp(u+k) = eu * exp(k)
    float euy = __expf(tfv.y);

    // eL = ew^CL, CL = 128 = 2^7 -> 7 squarings
    float eLx = ew.x, eLy = ew.y;
    #pragma unroll
    for (int i = 0; i < 7; ++i) { eLx *= eLx; eLy *= eLy; }

    // Prefix state entering chunk c: combine chunk sums 0..c-1 (L2 hits).
    float ax = 0.0f, ay = 0.0f, bx = 0.0f, by = 0.0f;
    int sbase = (b << (CSHIFT_ + H2SHIFT_)) + h2;      // (b*NC + 0)*H2 + h2
    for (int cc = 0; cc < c; ++cc) {
        float2 cA = g_cA[sbase + (cc << H2SHIFT_)];
        float2 cB = g_cB[sbase + (cc << H2SHIFT_)];
        ax = fmaf(eLx, ax, cA.x);
        ay = fmaf(eLy, ay, cA.y);
        bx = fmaf(eLx, bx, cB.x);
        by = fmaf(eLy, by, cB.y);
    }

    size_t base2 = ((size_t)b * T_ + (size_t)c * CL_) * H2_ + h2;
    const float2* kp = (const float2*)k + base2;
    const float2* vp = (const float2*)v + base2;
    float2*       op = (float2*)out + base2;

    #pragma unroll 4
    for (int t = 0; t < CL_; ++t) {
        float2 kk = __ldg(kp + (size_t)t * H2_);
        float2 vv = __ldg(vp + (size_t)t * H2_);
        float ekx = __expf(kk.x);
        float eky = __expf(kk.y);
        float eukx = eux * ekx;
        float euky = euy * eky;
        float2 o;
        o.x = __fdividef(ax + eukx * vv.x, (bx + eukx) + 1e-8f);
        o.y = __fdividef(ay + euky * vv.y, (by + euky) + 1e-8f);
        op[(size_t)t * H2_] = o;
        ax = fmaf(ew.x, ax, ekx * vv.x);
        ay = fmaf(ew.y, ay, eky * vv.y);
        bx = fmaf(ew.x, bx, ekx);
        by = fmaf(ew.y, by, eky);
    }

    // Final carried state from the last chunk.
    if (write_ab && c == (NC_ - 1)) {
        ((float2*)outA)[b * H2_ + h2] = make_float2(ax, ay);
        ((float2*)outB)[b * H2_ + h2] = make_float2(bx, by);
    }
}

// ---------------------------------------------------------------------------
// Launch. Inputs (metadata order): k, v, time_decay, time_first.
// Output: flattened tuple (output[B,T,H], a[B,H], b[B,H]) if out_size covers
// it; otherwise just output.
// ---------------------------------------------------------------------------
extern "C" void kernel_launch(void* const* d_in, const int* in_sizes, int n_in,
                              void* d_out, int out_size)
{
    const float* k  = (const float*)d_in[0];
    const float* v  = (const float*)d_in[1];
    const float* td = (const float*)d_in[2];
    const float* tf = (const float*)d_in[3];

    float* out = (float*)d_out;
    const long long main_elems = (long long)B_ * T_ * H_;
    int write_ab = (out_size >= (int)(main_elems + 2LL * B_ * H_)) ? 1 : 0;
    float* outA = out + main_elems;
    float* outB = outA + (B_ * H_);

    const int n = B_ * NC_ * H2_;          // 131072 threads
    wkv_sums<<<n / 256, 256>>>(k, v, td);
    wkv_out<<<n / 256, 256>>>(k, v, td, tf, out, outA, outB, write_ab);
}